// round 1
// baseline (speedup 1.0000x reference)
#include <cuda_runtime.h>
#include <math.h>
#include <stdint.h>

// ---------------- problem constants ----------------
#define BATCH 4
#define SEQ   2048
#define HID   2048
#define NEXP  32
#define INTER 2048
#define TOPK  4
#define NTOK  (BATCH*SEQ)          // 8192
#define NPAIR (NTOK*TOPK)          // 32768
#define MAXTILES (NPAIR/128 + NEXP) // 288

// ---------------- GEMM tiling ----------------
#define BM 128
#define BN 128
#define BK 16
#define PADK 20   // padded row stride (floats) in smem: 80B, 16B-aligned, conflict-friendly

// ---------------- device scratch (static: no allocation allowed) ----------------
__device__ int   g_counts[NEXP];
__device__ int   g_fill[NEXP];
__device__ int   g_offsets[NEXP+1];
__device__ int   g_topk_ids[NPAIR];
__device__ float g_topk_w[NPAIR];
__device__ int   g_perm_token[NPAIR];
__device__ float g_pair_w[NPAIR];
__device__ int   g_pair_pos[NPAIR];
__device__ int   g_tile_expert[MAXTILES];
__device__ int   g_tile_row0[MAXTILES];
__device__ int   g_num_tiles;

__device__ float g_gu[134217728];      // NPAIR * 2*INTER  (512 MB)
__device__ float g_inter[67108864];    // NPAIR * INTER    (256 MB)
__device__ float g_pair_out[67108864]; // NPAIR * HID      (256 MB)

// ---------------- helpers ----------------
__device__ __forceinline__ uint32_t f2tf32(float x) {
    uint32_t r;
    asm("cvt.rna.tf32.f32 %0, %1;" : "=r"(r) : "f"(x));
    return r;
}

__device__ __forceinline__ void mma_tf32(float* c, const uint32_t* a, const uint32_t* b) {
    asm volatile(
        "mma.sync.aligned.m16n8k8.row.col.f32.tf32.tf32.f32 "
        "{%0,%1,%2,%3}, {%4,%5,%6,%7}, {%8,%9}, {%0,%1,%2,%3};\n"
        : "+f"(c[0]), "+f"(c[1]), "+f"(c[2]), "+f"(c[3])
        : "r"(a[0]), "r"(a[1]), "r"(a[2]), "r"(a[3]),
          "r"(b[0]), "r"(b[1]));
}

__device__ __forceinline__ void cp16(float* dst_smem, const float* src_gmem, bool pred) {
    uint32_t s = (uint32_t)__cvta_generic_to_shared(dst_smem);
    int sz = pred ? 16 : 0;  // src_size=0 -> zero-fill 16B
    asm volatile("cp.async.cg.shared.global [%0], [%1], 16, %2;\n"
                 :: "r"(s), "l"(src_gmem), "r"(sz));
}

// ---------------- routing ----------------
__global__ void route_kernel(const float* __restrict__ logits) {
    int t = blockIdx.x * blockDim.x + threadIdx.x;
    if (t >= NTOK) return;
    const float* row = logits + (size_t)t * NEXP;

    float v[TOPK]; int id[TOPK];
    #pragma unroll
    for (int k = 0; k < TOPK; k++) { v[k] = -1e30f; id[k] = 0; }

    for (int e = 0; e < NEXP; e++) {
        float x = row[e];
        if (x > v[TOPK-1]) {
            int p = TOPK - 1;
            while (p > 0 && x > v[p-1]) { v[p] = v[p-1]; id[p] = id[p-1]; p--; }
            v[p] = x; id[p] = e;
        }
    }
    float w[TOPK]; float s = 0.f;
    #pragma unroll
    for (int k = 0; k < TOPK; k++) { w[k] = expf(v[k] - v[0]); s += w[k]; }
    float inv = 1.f / s;
    #pragma unroll
    for (int k = 0; k < TOPK; k++) {
        g_topk_ids[t*TOPK + k] = id[k];
        g_topk_w[t*TOPK + k]   = w[k] * inv;
        atomicAdd(&g_counts[id[k]], 1);
    }
}

__global__ void zero_kernel() {
    int i = threadIdx.x;
    if (i < NEXP) { g_counts[i] = 0; g_fill[i] = 0; }
}

__global__ void scan_tiles_kernel() {
    if (threadIdx.x != 0) return;
    int off = 0, nt = 0;
    for (int e = 0; e < NEXP; e++) {
        g_offsets[e] = off;
        int c = g_counts[e];
        for (int r = 0; r < c; r += BM) {
            g_tile_expert[nt] = e;
            g_tile_row0[nt]   = off + r;
            nt++;
        }
        off += c;
    }
    g_offsets[NEXP] = off;
    g_num_tiles = nt;
}

__global__ void scatter_kernel() {
    int i = blockIdx.x * blockDim.x + threadIdx.x;
    if (i >= NPAIR) return;
    int e = g_topk_ids[i];
    int pos = g_offsets[e] + atomicAdd(&g_fill[e], 1);
    g_perm_token[pos] = i >> 2;
    g_pair_w[pos]     = g_topk_w[i];
    g_pair_pos[i]     = pos;
}

// ---------------- grouped NT GEMM (tf32 mma.sync) ----------------
// MODE 1: GU[pos, 0:4096]   = gather(x)[pos,:] @ w13[e]^T        (N=4096, K=2048)
// MODE 2: PO[pos, 0:2048]   = (inter[pos,:] @ w2[e]^T) * pair_w  (N=2048, K=2048)
template<int MODE>
__global__ __launch_bounds__(256, 2)
void gemm_nt(const float* __restrict__ Ain, const float* __restrict__ Wall) {
    constexpr int NTOT = (MODE == 1) ? 2*INTER : HID;
    constexpr int KD   = (MODE == 1) ? HID : INTER;
    constexpr int KT   = KD / BK;

    int tile = blockIdx.x;
    if (tile >= g_num_tiles) return;
    int e    = g_tile_expert[tile];
    int row0 = g_tile_row0[tile];
    int m_valid = g_offsets[e+1] - row0;
    if (m_valid > BM) m_valid = BM;
    int n0 = blockIdx.y * BN;

    __shared__ __align__(16) float As[2][BM*PADK];
    __shared__ __align__(16) float Bs[2][BM*PADK];
    __shared__ int s_arow[BM];

    int tid = threadIdx.x;
    const float* A = (MODE == 1) ? Ain : g_inter;

    for (int r = tid; r < BM; r += 256) {
        int gr = -1;
        if (r < m_valid) gr = (MODE == 1) ? g_perm_token[row0 + r] : (row0 + r);
        s_arow[r] = gr;
    }
    __syncthreads();

    const float* Wp = Wall + (size_t)e * NTOT * KD + (size_t)n0 * KD;

    int wid = tid >> 5, lane = tid & 31;
    int warp_m = wid >> 2, warp_n = wid & 3;       // 2 x 4 warps -> 64x32 warp tiles
    int g = lane >> 2, q = lane & 3;

    float acc[4][4][4];
    #pragma unroll
    for (int a = 0; a < 4; a++)
        #pragma unroll
        for (int b = 0; b < 4; b++)
            #pragma unroll
            for (int c = 0; c < 4; c++) acc[a][b][c] = 0.f;

    // ---- stage loader ----
    auto load_stage = [&](int stage, int kt) {
        float* Ad = As[stage];
        float* Bd = Bs[stage];
        #pragma unroll
        for (int i = 0; i < 2; i++) {
            int idx = tid + i*256;
            int r = idx >> 2, seg = idx & 3;
            int gr = s_arow[r];
            const float* src = A + (size_t)(gr < 0 ? 0 : gr) * KD + kt + seg*4;
            cp16(Ad + r*PADK + seg*4, src, gr >= 0);
        }
        #pragma unroll
        for (int i = 0; i < 2; i++) {
            int idx = tid + i*256;
            int r = idx >> 2, seg = idx & 3;
            const float* src = Wp + (size_t)r * KD + kt + seg*4;
            cp16(Bd + r*PADK + seg*4, src, true);
        }
        asm volatile("cp.async.commit_group;\n");
    };

    load_stage(0, 0);

    for (int it = 0; it < KT; it++) {
        int cur = it & 1;
        if (it + 1 < KT) {
            load_stage(cur ^ 1, (it + 1) * BK);
            asm volatile("cp.async.wait_group 1;\n");
        } else {
            asm volatile("cp.async.wait_group 0;\n");
        }
        __syncthreads();

        const float* Ab = As[cur];
        const float* Bb = Bs[cur];
        #pragma unroll
        for (int ks = 0; ks < 2; ks++) {
            int k0 = ks * 8;
            uint32_t af[4][4], bf[4][2];
            #pragma unroll
            for (int mt = 0; mt < 4; mt++) {
                int r = warp_m*64 + mt*16 + g;
                af[mt][0] = f2tf32(Ab[(r    )*PADK + k0 + q    ]);
                af[mt][1] = f2tf32(Ab[(r + 8)*PADK + k0 + q    ]);
                af[mt][2] = f2tf32(Ab[(r    )*PADK + k0 + q + 4]);
                af[mt][3] = f2tf32(Ab[(r + 8)*PADK + k0 + q + 4]);
            }
            #pragma unroll
            for (int nt = 0; nt < 4; nt++) {
                int bn = warp_n*32 + nt*8 + g;
                bf[nt][0] = f2tf32(Bb[bn*PADK + k0 + q    ]);
                bf[nt][1] = f2tf32(Bb[bn*PADK + k0 + q + 4]);
            }
            #pragma unroll
            for (int mt = 0; mt < 4; mt++)
                #pragma unroll
                for (int nt = 0; nt < 4; nt++)
                    mma_tf32(acc[mt][nt], af[mt], bf[nt]);
        }
        __syncthreads();
    }

    // ---- epilogue ----
    #pragma unroll
    for (int mt = 0; mt < 4; mt++) {
        #pragma unroll
        for (int h = 0; h < 2; h++) {
            int lr = warp_m*64 + mt*16 + g + h*8;
            if (lr < m_valid) {
                int grow = row0 + lr;
                float sc = 1.f;
                if (MODE == 2) sc = g_pair_w[grow];
                float* Crow = ((MODE == 1) ? g_gu : g_pair_out)
                              + (size_t)grow * NTOT + n0 + warp_n*32;
                #pragma unroll
                for (int nt = 0; nt < 4; nt++) {
                    float2 v;
                    v.x = acc[mt][nt][h*2 + 0] * sc;
                    v.y = acc[mt][nt][h*2 + 1] * sc;
                    *(float2*)(Crow + nt*8 + 2*q) = v;
                }
            }
        }
    }
}

// ---------------- silu(gate) * up ----------------
__global__ void silu_kernel() {
    size_t i4 = (size_t)blockIdx.x * blockDim.x + threadIdx.x;
    const size_t total = (size_t)NPAIR * (INTER/4);
    if (i4 >= total) return;
    size_t p = i4 / (INTER/4);
    int c = (int)(i4 % (INTER/4));
    const float4* gu = (const float4*)(g_gu + p * (size_t)(2*INTER));
    float4 gv = gu[c];
    float4 uv = gu[INTER/4 + c];
    float4 o;
    o.x = gv.x / (1.f + expf(-gv.x)) * uv.x;
    o.y = gv.y / (1.f + expf(-gv.y)) * uv.y;
    o.z = gv.z / (1.f + expf(-gv.z)) * uv.z;
    o.w = gv.w / (1.f + expf(-gv.w)) * uv.w;
    ((float4*)(g_inter + p * (size_t)INTER))[c] = o;
}

// ---------------- deterministic combine ----------------
__global__ void combine_kernel(float* __restrict__ out) {
    int t = blockIdx.x;
    int p0 = g_pair_pos[t*4 + 0];
    int p1 = g_pair_pos[t*4 + 1];
    int p2 = g_pair_pos[t*4 + 2];
    int p3 = g_pair_pos[t*4 + 3];
    const float4* r0 = (const float4*)(g_pair_out + (size_t)p0 * HID);
    const float4* r1 = (const float4*)(g_pair_out + (size_t)p1 * HID);
    const float4* r2 = (const float4*)(g_pair_out + (size_t)p2 * HID);
    const float4* r3 = (const float4*)(g_pair_out + (size_t)p3 * HID);
    float4* o = (float4*)(out + (size_t)t * HID);
    for (int c = threadIdx.x; c < HID/4; c += blockDim.x) {
        float4 a = r0[c], b = r1[c], cc = r2[c], d = r3[c];
        float4 v;
        v.x = a.x + b.x + cc.x + d.x;
        v.y = a.y + b.y + cc.y + d.y;
        v.z = a.z + b.z + cc.z + d.z;
        v.w = a.w + b.w + cc.w + d.w;
        o[c] = v;
    }
}

// ---------------- launch ----------------
extern "C" void kernel_launch(void* const* d_in, const int* in_sizes, int n_in,
                              void* d_out, int out_size) {
    const float* x      = (const float*)d_in[0];
    const float* logits = (const float*)d_in[1];
    const float* w13    = (const float*)d_in[2];
    const float* w2     = (const float*)d_in[3];
    float* out = (float*)d_out;

    zero_kernel<<<1, 32>>>();
    route_kernel<<<(NTOK + 255)/256, 256>>>(logits);
    scan_tiles_kernel<<<1, 1>>>();
    scatter_kernel<<<(NPAIR + 255)/256, 256>>>();

    gemm_nt<1><<<dim3(MAXTILES, (2*INTER)/BN), 256>>>(x, w13);

    {
        size_t total = (size_t)NPAIR * (INTER/4);
        int blocks = (int)((total + 255) / 256);
        silu_kernel<<<blocks, 256>>>();
    }

    gemm_nt<2><<<dim3(MAXTILES, HID/BN), 256>>>(nullptr, w2);

    combine_kernel<<<NTOK, 128>>>(out);
}